// round 12
// baseline (speedup 1.0000x reference)
#include <cuda_runtime.h>
#include <cuda_bf16.h>
#include <stdint.h>

#define NB 2
#define NH 48
#define NW 48
#define ND 24
#define NA 9
#define NK 20
#define TOTAL  497664            // NH*NW*ND*NA
#define HWD    55296             // NH*NW*ND
#define OUTTOT 995328            // NB*NA*HWD
#define NUMFG 128
#define RPNB  256
#define NBINS 65536
#define CAP   4096
#define BPB   243                // blocks per batch in passB (2048 anchors each)

#define OFF_BT  995328
#define OFF_IW  (OFF_BT + 5971968)
#define OFF_OW  (OFF_IW + 5971968)

// ------------- device scratch (zero-init at load; reset by passD) ---------------
__device__ int                g_gtmax[NB * NK];     // float bits of max ov (direct store)
__device__ unsigned int       g_mask[NB * TOTAL];   // bit k set => ov(anchor, gt k) > 0
__device__ signed char        g_label[NB * TOTAL];
__device__ unsigned char      g_amax[NB * TOTAL];
__device__ unsigned int       g_hist[4 * NBINS];
__device__ unsigned int       g_csum[256];
__device__ unsigned int       g_bin[4];
__device__ int                g_m[4];
__device__ int                g_keep[4];            // 1 => keep all (0-init = active)
__device__ int                g_ncand[4];
__device__ unsigned long long g_cand[4 * CAP];
__device__ unsigned long long g_thresh[4];
__device__ int                g_done_u;
__device__ float              g_wval;

// IoU with strict _rn intrinsics: bitwise identical in passA and passB.
__device__ __forceinline__ float f_ov(float ax1, float ay1, float ax2, float ay2,
                                      float az1, float az2, float aarea,
                                      const float* __restrict__ g) {
    float iw = __fadd_rn(__fsub_rn(fminf(ax2, g[2]), fmaxf(ax1, g[0])), 1.0f);
    if (iw <= 0.0f) return 0.0f;
    float ih = __fadd_rn(__fsub_rn(fminf(ay2, g[3]), fmaxf(ay1, g[1])), 1.0f);
    if (ih <= 0.0f) return 0.0f;
    float idp = __fadd_rn(__fsub_rn(fminf(az2, g[5]), fmaxf(az1, g[4])), 1.0f);
    if (idp <= 0.0f) return 0.0f;
    float inter = __fmul_rn(__fmul_rn(iw, ih), idp);
    float den   = __fsub_rn(__fadd_rn(aarea, g[6]), inter);
    return __fdiv_rn(inter, den);
}

__device__ __forceinline__ float f_area(float x1, float y1, float x2, float y2,
                                        float z1, float z2) {
    float aw = __fadd_rn(__fsub_rn(x2, x1), 1.0f);
    float ah = __fadd_rn(__fsub_rn(y2, y1), 1.0f);
    float ad = __fadd_rn(__fsub_rn(z2, z1), 1.0f);
    return __fmul_rn(__fmul_rn(aw, ah), ad);
}

__device__ __forceinline__ void build_sgt(float* sgt, const float* __restrict__ gt, int b) {
    int tid = threadIdx.x;
    if (tid < NK) {
        const float* g = gt + (b * NK + tid) * 7;
        float x1 = g[0], y1 = g[1], x2 = g[2], y2 = g[3], z1 = g[4], z2 = g[5];
        float gw = __fadd_rn(__fsub_rn(x2, x1), 1.0f);
        float gh = __fadd_rn(__fsub_rn(y2, y1), 1.0f);
        float gd = __fadd_rn(__fsub_rn(z2, z1), 1.0f);
        if (gw == 1.0f && gh == 1.0f && gd == 1.0f) { x2 = -1e9f; }   // zero-size => ov 0
        float* o = sgt + tid * 7;
        o[0] = x1; o[1] = y1; o[2] = x2; o[3] = y2; o[4] = z1; o[5] = z2;
        o[6] = __fmul_rn(__fmul_rn(gw, gh), gd);
    }
}

// ========== passA: hist zero (all 256 blocks) + windowed gt-max / mask scatter ===
__global__ void __launch_bounds__(256) k_passA(const float* __restrict__ gt,
                                               const float* __restrict__ im_info,
                                               const float* __restrict__ anchors) {
    // zero histogram: grid is exactly 256 blocks -> 65536 uint4
    ((uint4*)g_hist)[blockIdx.x * 256 + threadIdx.x] = make_uint4(0u, 0u, 0u, 0u);
    if (blockIdx.x >= NB * NK) return;

    __shared__ float sanch[NA * 6];
    __shared__ float sg[7];
    __shared__ int   smax;
    int b = blockIdx.x / NK, k = blockIdx.x % NK;
    if (threadIdx.x < NA * 6) sanch[threadIdx.x] = anchors[threadIdx.x];
    if (threadIdx.x == 0) {
        const float* g = gt + (b * NK + k) * 7;
        float x1 = g[0], y1 = g[1], x2 = g[2], y2 = g[3], z1 = g[4], z2 = g[5];
        float gw = __fadd_rn(__fsub_rn(x2, x1), 1.0f);
        float gh = __fadd_rn(__fsub_rn(y2, y1), 1.0f);
        float gd = __fadd_rn(__fsub_rn(z2, z1), 1.0f);
        if (gw == 1.0f && gh == 1.0f && gd == 1.0f) { x2 = -1e9f; }
        sg[0] = x1; sg[1] = y1; sg[2] = x2; sg[3] = y2; sg[4] = z1; sg[5] = z2;
        sg[6] = __fmul_rn(__fmul_rn(gw, gh), gd);
        smax = 0;
    }
    __syncthreads();
    const float iH = im_info[0], iW = im_info[1], iD = im_info[2];
    unsigned kb = 1u << k;
    float vmax = 0.0f;

    for (int a = 0; a < NA; a++) {
        const float* an = sanch + a * 6;
        int wlo = max(0,      (int)floorf((sg[0] - 1.0f - an[2]) * 0.0625f) - 1);
        int whi = min(NW - 1, (int)floorf((sg[2] + 1.0f - an[0]) * 0.0625f) + 1);
        int hlo = max(0,      (int)floorf((sg[1] - 1.0f - an[3]) * 0.0625f) - 1);
        int hhi = min(NH - 1, (int)floorf((sg[3] + 1.0f - an[1]) * 0.0625f) + 1);
        int dlo = max(0,      (int)floorf((sg[4] - 1.0f - an[5]) * 0.0625f) - 1);
        int dhi = min(ND - 1, (int)floorf((sg[5] + 1.0f - an[4]) * 0.0625f) + 1);
        int nx = whi - wlo + 1, ny = hhi - hlo + 1, nz = dhi - dlo + 1;
        if (nx <= 0 || ny <= 0 || nz <= 0) continue;
        int vol = nx * ny * nz;
        for (int idx = threadIdx.x; idx < vol; idx += 256) {
            int x = idx % nx; int r = idx / nx;
            int y = r % ny;   int zc = r / ny;
            int w = wlo + x, h = hlo + y, d = dlo + zc;
            float shx = w * 16.0f, shy = h * 16.0f, shz = d * 16.0f;
            float ax1 = an[0] + shx, ay1 = an[1] + shy;
            float ax2 = an[2] + shx, ay2 = an[3] + shy;
            float az1 = an[4] + shz, az2 = an[5] + shz;
            float aarea = f_area(ax1, ay1, ax2, ay2, az1, az2);
            float ov = f_ov(ax1, ay1, ax2, ay2, az1, az2, aarea, sg);
            if (ov > 0.0f) {
                atomicOr(&g_mask[b * TOTAL + ((h * NW + w) * ND + d) * NA + a], kb);
                bool inside = (ax1 >= 0.0f) && (ay1 >= 0.0f) && (az1 >= 0.0f) &&
                              (ax2 < iW) && (ay2 < iH) && (az2 < iD);
                if (inside) vmax = fmaxf(vmax, ov);
            }
        }
    }
#pragma unroll
    for (int off = 16; off; off >>= 1) vmax = fmaxf(vmax, __shfl_xor_sync(0xFFFFFFFFu, vmax, off));
    if ((threadIdx.x & 31) == 0) atomicMax(&smax, __float_as_int(vmax));
    __syncthreads();
    if (threadIdx.x == 0) g_gtmax[b * NK + k] = smax;
}

// ================= passB: mask-sparse labels, argmax, histogram ==================
__global__ void __launch_bounds__(256, 4) k_passB(const float* __restrict__ gt,
                                                  const float* __restrict__ im_info,
                                                  const float* __restrict__ anchors,
                                                  const float* __restrict__ rfg,
                                                  const float* __restrict__ rbg) {
    int b    = blockIdx.x / BPB;
    int base = (blockIdx.x % BPB) * 2048;
    __shared__ float sgt[NK * 7];
    __shared__ float sgm[NK];
    __shared__ float sanch[NA * 6];
    build_sgt(sgt, gt, b);
    if (threadIdx.x < NK) {
        float gm = __int_as_float(g_gtmax[b * NK + threadIdx.x]);
        sgm[threadIdx.x] = (gm == 0.0f) ? 1e-5f : gm;
    }
    if (threadIdx.x < NA * 6) sanch[threadIdx.x] = anchors[threadIdx.x];
    __syncthreads();
    const float iH = im_info[0], iW = im_info[1], iD = im_info[2];

#pragma unroll 1
    for (int t = 0; t < 8; t++) {
        int i = base + t * 256 + threadIdx.x;
        int e = b * TOTAL + i;
        int a = i % NA; int q = i / NA;
        int d = q % ND; q /= ND;
        int w = q % NW; int h = q / NW;
        float shx = w * 16.0f, shy = h * 16.0f, shz = d * 16.0f;
        const float* an = sanch + a * 6;
        float ax1 = an[0] + shx, ay1 = an[1] + shy;
        float ax2 = an[2] + shx, ay2 = an[3] + shy;
        float az1 = an[4] + shz, az2 = an[5] + shz;
        bool inside = (ax1 >= 0.0f) && (ay1 >= 0.0f) && (az1 >= 0.0f) &&
                      (ax2 < iW) && (ay2 < iH) && (az2 < iD);
        signed char lab = -1;
        unsigned char am = 0;
        if (inside) {
            unsigned mk = g_mask[e];
            lab = 0;                                   // no overlapping gt => all ov 0 => bg
            if (mk) {
                float aarea = f_area(ax1, ay1, ax2, ay2, az1, az2);
                float best = -1.0f;
                int bi = 0;
                bool tie = false;
                do {
                    int k = __ffs(mk) - 1;
                    mk &= mk - 1;
                    float ov = f_ov(ax1, ay1, ax2, ay2, az1, az2, aarea, sgt + k * 7);
                    if (ov > best) { best = ov; bi = k; }
                    if (ov == sgm[k]) tie = true;
                } while (mk);
                lab = (tie || best >= 0.7f) ? 1 : ((best < 0.3f) ? 0 : -1);
                am = (unsigned char)bi;
            }
        }
        g_label[e] = lab;
        g_amax[e]  = am;

        if (lab == 1) {
            unsigned bin = __float_as_uint(rfg[e]) >> 16;
            atomicAdd(&g_hist[(b * 2) * NBINS + bin], 1u);
        } else if (lab == 0) {
            unsigned bin = __float_as_uint(rbg[e]) >> 16;
            atomicAdd(&g_hist[(b * 2 + 1) * NBINS + bin], 1u);
        }
    }
}

// ================= upd0: 256-block chunk sums + warp-parallel resolve ============
__global__ void __launch_bounds__(256) k_upd0() {
    int g = blockIdx.x >> 6;          // group 0..3
    int c = blockIdx.x & 63;          // chunk of 1024 bins
    const int tid = threadIdx.x;
    const int lane = tid & 31, wid = tid >> 5;

    uint4 v4 = ((const uint4*)(g_hist + g * NBINS + c * 1024))[tid];
    unsigned s = v4.x + v4.y + v4.z + v4.w;
#pragma unroll
    for (int off = 16; off; off >>= 1) s += __shfl_xor_sync(0xFFFFFFFFu, s, off);
    __shared__ unsigned wsum[8];
    __shared__ int slast;
    if (lane == 0) wsum[wid] = s;
    __syncthreads();
    if (tid == 0) {
        unsigned tot = 0;
#pragma unroll
        for (int i = 0; i < 8; i++) tot += wsum[i];
        g_csum[blockIdx.x] = tot;     // index = g*64 + c
        __threadfence();
        int o = atomicAdd(&g_done_u, 1);
        slast = (o == 255) ? 1 : 0;
    }
    __syncthreads();
    if (!slast) return;

    __shared__ unsigned scs[256];
    __shared__ unsigned stot[4];
    __shared__ unsigned sbins[4][1024];
    scs[tid] = g_csum[tid];
    __syncthreads();
    if (tid < 4) {
        unsigned t = 0;
        for (int j = 0; j < 64; j++) t += scs[tid * 64 + j];
        stot[tid] = t;
    }
    __syncthreads();
    if (tid == 0) {
        int fg1 = (int)stot[2]; if (fg1 > NUMFG) fg1 = NUMFG;
        int cap = RPNB - fg1;
        int bg1 = (int)stot[3]; if (bg1 > cap) bg1 = cap;
        int ne = fg1 + bg1;
        g_wval = 1.0f / (float)(ne > 0 ? ne : 1);
    }
    if (wid < 4) {
        int w = wid;
        unsigned total = stot[w];
        int m0;
        if ((w & 1) == 0) m0 = NUMFG;
        else { int fgc = (int)stot[w - 1]; int kept = (fgc < NUMFG) ? fgc : NUMFG; m0 = RPNB - kept; }

        if ((unsigned)m0 >= total) {
            if (lane == 0) { g_keep[w] = 1; g_thresh[w] = 0ULL; }
        } else {
            int cstar = 0; unsigned acc = 0;
            if (lane == 0) {
                for (int cc = 63; cc >= 0; cc--) {
                    unsigned cv = scs[w * 64 + cc];
                    if (acc + cv >= (unsigned)m0) { cstar = cc; break; }
                    acc += cv;
                }
            }
            cstar = __shfl_sync(0xFFFFFFFFu, cstar, 0);
            acc   = __shfl_sync(0xFFFFFFFFu, acc, 0);
            int m_rem = m0 - (int)acc;     // >= 1
            const unsigned* hb = g_hist + w * NBINS + cstar * 1024;
            for (int j = lane; j < 1024; j += 32) sbins[w][j] = hb[j];
            __syncwarp();
            unsigned accw = 0;
            for (int basei = 1023; basei >= 31; basei -= 32) {
                unsigned v = sbins[w][basei - lane];
                unsigned inc = v;
#pragma unroll
                for (int off = 1; off < 32; off <<= 1) {
                    unsigned u = __shfl_up_sync(0xFFFFFFFFu, inc, off);
                    if (lane >= off) inc += u;
                }
                unsigned tot32 = __shfl_sync(0xFFFFFFFFu, inc, 31);
                if (accw + tot32 >= (unsigned)m_rem) {
                    unsigned incl = accw + inc;
                    unsigned excl = incl - v;
                    if (excl < (unsigned)m_rem && (unsigned)m_rem <= incl) {
                        g_bin[w] = (unsigned)(cstar * 1024 + basei - lane);
                        g_m[w]   = m_rem - (int)excl;
                    }
                    break;
                }
                accw += tot32;
            }
        }
    }
}

// ================= collect: gather keys in the threshold bin =====================
__global__ void __launch_bounds__(256) k_collect(const float* __restrict__ rfg,
                                                 const float* __restrict__ rbg) {
    int e = blockIdx.x * 256 + threadIdx.x;
    int lab = g_label[e];
    if (lab < 0) return;
    int b = (e >= TOTAL) ? 1 : 0;
    unsigned i = (unsigned)(e - b * TOTAL);
    int grp = b * 2 + (lab == 0 ? 1 : 0);
    if (g_keep[grp]) return;
    float rv = (lab == 1) ? rfg[e] : rbg[e];
    unsigned rb = __float_as_uint(rv);
    if ((rb >> 16) != g_bin[grp]) return;
    unsigned long long key = ((unsigned long long)rb << 32) | (unsigned)(~i);
    int pos = atomicAdd(&g_ncand[grp], 1);
    if (pos < CAP) g_cand[grp * CAP + pos] = key;
}

// ================= finish: exact m-th largest within the bin =====================
__global__ void __launch_bounds__(256) k_finish() {
    int grp = blockIdx.x;
    if (g_keep[grp]) return;
    __shared__ unsigned long long sk[CAP];
    int n = g_ncand[grp];
    if (n > CAP) n = CAP;
    int m = g_m[grp];
    for (int i = threadIdx.x; i < n; i += 256) sk[i] = g_cand[grp * CAP + i];
    __syncthreads();
    for (int i = threadIdx.x; i < n; i += 256) {
        unsigned long long k = sk[i];
        int cg = 0;
        for (int j = 0; j < n; j++) cg += (sk[j] > k) ? 1 : 0;
        if (cg == m - 1) g_thresh[grp] = k;
    }
}

// ================= passD: outputs + mask clear + state reset =====================
__global__ void __launch_bounds__(256) k_passD(const float* __restrict__ gt,
                                               const float* __restrict__ im_info,
                                               const float* __restrict__ anchors,
                                               const float* __restrict__ rfg,
                                               const float* __restrict__ rbg,
                                               float* __restrict__ out) {
    int tid = blockIdx.x * 256 + threadIdx.x;
    int idx = tid * 4;
    int d0 = idx % ND; int q = idx / ND;
    int w = q % NW; q /= NW;
    int h = q % NH; q /= NH;
    int a = q % NA; int b = q / NA;
    int pix0 = (h * NW + w) * ND + d0;

    __shared__ float sanch[NA * 6];
    __shared__ float sder[NA * 9];
    __shared__ float sgtd[NB * NK * 6];
    __shared__ unsigned long long sth[4];
    if (threadIdx.x < NA * 6) sanch[threadIdx.x] = anchors[threadIdx.x];
    if (threadIdx.x < 4) sth[threadIdx.x] = g_thresh[threadIdx.x];
    if (threadIdx.x >= 128 && threadIdx.x < 128 + NA) {
        int aa = threadIdx.x - 128;
        const float* an = anchors + aa * 6;
        float ew = an[2] - an[0] + 1.0f;
        float eh = an[3] - an[1] + 1.0f;
        float ed = an[5] - an[4] + 1.0f;
        float* o = sder + aa * 9;
        o[0] = an[0] + 0.5f * (ew - 1.0f);
        o[1] = an[1] + 0.5f * (eh - 1.0f);
        o[2] = an[4] + 0.5f * (ed - 1.0f);
        o[3] = 1.0f / ew; o[4] = 1.0f / eh; o[5] = 1.0f / ed;
        o[6] = logf(ew); o[7] = logf(eh); o[8] = logf(ed);
    }
    if (threadIdx.x >= 160 && threadIdx.x < 160 + NB * NK) {
        int j = threadIdx.x - 160;
        const float* g = gt + j * 7;
        float gw = g[2] - g[0] + 1.0f, gh = g[3] - g[1] + 1.0f, gd = g[5] - g[4] + 1.0f;
        float* o = sgtd + j * 6;
        o[0] = g[0] + 0.5f * (gw - 1.0f);
        o[1] = g[1] + 0.5f * (gh - 1.0f);
        o[2] = g[4] + 0.5f * (gd - 1.0f);
        o[3] = logf(gw); o[4] = logf(gh); o[5] = logf(gd);
    }
    __syncthreads();

    const float iH = im_info[0], iW = im_info[1], iD = im_info[2];
    const float* an = sanch + a * 6;
    const float* ad = sder + a * 9;
    float shx = w * 16.0f, shy = h * 16.0f;
    float ax1 = an[0] + shx, ay1 = an[1] + shy;
    float ax2 = an[2] + shx, ay2 = an[3] + shy;
    bool inxy = (ax1 >= 0.0f) && (ay1 >= 0.0f) && (ax2 < iW) && (ay2 < iH);
    float wv = g_wval;

    float lb[4], ivv[4], ovv[4];
    float T[6][4];
#pragma unroll
    for (int j = 0; j < 4; j++) {
        float shz = (float)(d0 + j) * 16.0f;
        float az1 = an[4] + shz, az2 = an[5] + shz;
        bool inside = inxy && (az1 >= 0.0f) && (az2 < iD);
        int ia = (pix0 + j) * NA + a;
        int e  = b * TOTAL + ia;
        int lab = (int)g_label[e];
        if (lab >= 0) {
            int grp = b * 2 + (lab == 0 ? 1 : 0);
            float rv = (lab == 1) ? rfg[e] : rbg[e];
            unsigned long long key = ((unsigned long long)__float_as_uint(rv) << 32) | (unsigned)(~(unsigned)ia);
            if (key < sth[grp]) lab = -1;
        }
        float t0 = 0.0f, t1 = 0.0f, t2 = 0.0f, t3 = 0.0f, t4 = 0.0f, t5 = 0.0f;
        if (inside) {
            int am = (int)g_amax[e];
            const float* gd = sgtd + (b * NK + am) * 6;
            t0 = (gd[0] - ad[0] - shx) * ad[3];
            t1 = (gd[1] - ad[1] - shy) * ad[4];
            t2 = (gd[2] - ad[2] - shz) * ad[5];
            t3 = gd[3] - ad[6];
            t4 = gd[4] - ad[7];
            t5 = gd[5] - ad[8];
        }
        T[0][j] = t0; T[1][j] = t1; T[2][j] = t2;
        T[3][j] = t3; T[4][j] = t4; T[5][j] = t5;
        lb[j]  = (float)lab;
        ivv[j] = (lab == 1) ? 1.0f : 0.0f;
        ovv[j] = (lab >= 0) ? wv : 0.0f;
    }

    *(float4*)(out + idx) = make_float4(lb[0], lb[1], lb[2], lb[3]);
    long long base = (long long)(b * 54 + a * 6) * HWD + pix0;
    float* bt = out + OFF_BT + base;
#pragma unroll
    for (int c = 0; c < 6; c++)
        *(float4*)(bt + c * HWD) = make_float4(T[c][0], T[c][1], T[c][2], T[c][3]);
    float* iwp = out + OFF_IW + base;
    float* owp = out + OFF_OW + base;
    float4 iv = make_float4(ivv[0], ivv[1], ivv[2], ivv[3]);
    float4 ov = make_float4(ovv[0], ovv[1], ovv[2], ovv[3]);
#pragma unroll
    for (int c = 0; c < 6; c++) {
        *(float4*)(iwp + c * HWD) = iv;
        *(float4*)(owp + c * HWD) = ov;
    }

    // ---- clear mask for the next graph replay (exact fit: 248832 uint4) ----
    ((uint4*)g_mask)[tid] = make_uint4(0u, 0u, 0u, 0u);

    // ---- state reset for the next graph replay (block 0) ----
    if (blockIdx.x == 0) {
        int t = threadIdx.x;
        if (t >= 72 && t < 76)  g_ncand[t - 72] = 0;
        if (t >= 80 && t < 84)  g_keep[t - 80] = 0;
        if (t == 90) g_done_u = 0;
    }
}

// ---------------- launch ----------------
extern "C" void kernel_launch(void* const* d_in, const int* in_sizes, int n_in,
                              void* d_out, int out_size) {
    const float* gt      = (const float*)d_in[1];
    const float* im_info = (const float*)d_in[2];
    const float* anchors = (const float*)d_in[4];
    const float* rfg     = (const float*)d_in[5];
    const float* rbg     = (const float*)d_in[6];
    float* out           = (float*)d_out;

    k_passA<<<256, 256>>>(gt, im_info, anchors);
    k_passB<<<NB * BPB, 256>>>(gt, im_info, anchors, rfg, rbg);
    k_upd0<<<256, 256>>>();
    k_collect<<<(NB * TOTAL) / 256, 256>>>(rfg, rbg);
    k_finish<<<4, 256>>>();
    k_passD<<<OUTTOT / 4 / 256, 256>>>(gt, im_info, anchors, rfg, rbg, out);
}

// round 13
// speedup vs baseline: 1.4332x; 1.4332x over previous
#include <cuda_runtime.h>
#include <cuda_bf16.h>
#include <stdint.h>

#define NB 2
#define NH 48
#define NW 48
#define ND 24
#define NA 9
#define NK 20
#define TOTAL  497664            // NH*NW*ND*NA
#define HWD    55296             // NH*NW*ND
#define OUTTOT 995328            // NB*NA*HWD
#define NUMFG 128
#define RPNB  256
#define NBINS 65536
#define CAP   4096
#define BPB   243                // blocks per batch in passB (2048 anchors each)

#define OFF_BT  995328
#define OFF_IW  (OFF_BT + 5971968)
#define OFF_OW  (OFF_IW + 5971968)

// ------------- device scratch (zero-init at load; reset by passD block 0) -------
__device__ int                g_gtmax[NB * NK];     // float bits of max ov (>=0); 0-init ok
__device__ signed char        g_label[NB * TOTAL];
__device__ unsigned char      g_amax[NB * TOTAL];
__device__ unsigned int       g_hist[4 * NBINS];
__device__ unsigned int       g_csum[256];
__device__ unsigned int       g_bin[4];
__device__ int                g_m[4];
__device__ int                g_keep[4];            // 1 => keep all (0-init = active)
__device__ int                g_ncand[4];
__device__ unsigned long long g_cand[4 * CAP];
__device__ unsigned long long g_thresh[4];
__device__ int                g_done_u;
__device__ float              g_wval;

// IoU with strict _rn intrinsics: bitwise identical in passA and passB.
__device__ __forceinline__ float f_ov(float ax1, float ay1, float ax2, float ay2,
                                      float az1, float az2, float aarea,
                                      const float* __restrict__ g) {
    float iw = __fadd_rn(__fsub_rn(fminf(ax2, g[2]), fmaxf(ax1, g[0])), 1.0f);
    if (iw <= 0.0f) return 0.0f;
    float ih = __fadd_rn(__fsub_rn(fminf(ay2, g[3]), fmaxf(ay1, g[1])), 1.0f);
    if (ih <= 0.0f) return 0.0f;
    float idp = __fadd_rn(__fsub_rn(fminf(az2, g[5]), fmaxf(az1, g[4])), 1.0f);
    if (idp <= 0.0f) return 0.0f;
    float inter = __fmul_rn(__fmul_rn(iw, ih), idp);
    float den   = __fsub_rn(__fadd_rn(aarea, g[6]), inter);
    return __fdiv_rn(inter, den);
}

__device__ __forceinline__ float f_area(float x1, float y1, float x2, float y2,
                                        float z1, float z2) {
    float aw = __fadd_rn(__fsub_rn(x2, x1), 1.0f);
    float ah = __fadd_rn(__fsub_rn(y2, y1), 1.0f);
    float ad = __fadd_rn(__fsub_rn(z2, z1), 1.0f);
    return __fmul_rn(__fmul_rn(aw, ah), ad);
}

__device__ __forceinline__ void build_sgt(float* sgt, const float* __restrict__ gt, int b) {
    int tid = threadIdx.x;
    if (tid < NK) {
        const float* g = gt + (b * NK + tid) * 7;
        float x1 = g[0], y1 = g[1], x2 = g[2], y2 = g[3], z1 = g[4], z2 = g[5];
        float gw = __fadd_rn(__fsub_rn(x2, x1), 1.0f);
        float gh = __fadd_rn(__fsub_rn(y2, y1), 1.0f);
        float gd = __fadd_rn(__fsub_rn(z2, z1), 1.0f);
        if (gw == 1.0f && gh == 1.0f && gd == 1.0f) { x2 = -1e9f; }   // zero-size => ov 0
        float* o = sgt + tid * 7;
        o[0] = x1; o[1] = y1; o[2] = x2; o[3] = y2; o[4] = z1; o[5] = z2;
        o[6] = __fmul_rn(__fmul_rn(gw, gh), gd);
    }
}

// ===== passA: hist zero (512 blocks x 128 uint4) + windowed per-(b,gt,a) max =====
__global__ void __launch_bounds__(256) k_passA(const float* __restrict__ gt,
                                               const float* __restrict__ im_info,
                                               const float* __restrict__ anchors) {
    // zero histogram: 512 blocks x 128 uint4 = 65536 uint4
    if (threadIdx.x < 128)
        ((uint4*)g_hist)[blockIdx.x * 128 + threadIdx.x] = make_uint4(0u, 0u, 0u, 0u);
    if (blockIdx.x >= NB * NK * NA) return;

    int b = blockIdx.x / (NK * NA);
    int k = (blockIdx.x / NA) % NK;
    int a = blockIdx.x % NA;

    __shared__ float sg[7];
    __shared__ float san[6];
    __shared__ int   smax;
    if (threadIdx.x == 0) {
        const float* g = gt + (b * NK + k) * 7;
        float x1 = g[0], y1 = g[1], x2 = g[2], y2 = g[3], z1 = g[4], z2 = g[5];
        float gw = __fadd_rn(__fsub_rn(x2, x1), 1.0f);
        float gh = __fadd_rn(__fsub_rn(y2, y1), 1.0f);
        float gd = __fadd_rn(__fsub_rn(z2, z1), 1.0f);
        if (gw == 1.0f && gh == 1.0f && gd == 1.0f) { x2 = -1e9f; }
        sg[0] = x1; sg[1] = y1; sg[2] = x2; sg[3] = y2; sg[4] = z1; sg[5] = z2;
        sg[6] = __fmul_rn(__fmul_rn(gw, gh), gd);
        smax = 0;
    }
    if (threadIdx.x >= 32 && threadIdx.x < 38) san[threadIdx.x - 32] = anchors[a * 6 + threadIdx.x - 32];
    __syncthreads();

    // shift window where ov>0 is possible (±1 cell slack; validated in R12)
    int wlo = max(0,      (int)floorf((sg[0] - 1.0f - san[2]) * 0.0625f) - 1);
    int whi = min(NW - 1, (int)floorf((sg[2] + 1.0f - san[0]) * 0.0625f) + 1);
    int hlo = max(0,      (int)floorf((sg[1] - 1.0f - san[3]) * 0.0625f) - 1);
    int hhi = min(NH - 1, (int)floorf((sg[3] + 1.0f - san[1]) * 0.0625f) + 1);
    int dlo = max(0,      (int)floorf((sg[4] - 1.0f - san[5]) * 0.0625f) - 1);
    int dhi = min(ND - 1, (int)floorf((sg[5] + 1.0f - san[4]) * 0.0625f) + 1);
    int nx = whi - wlo + 1, ny = hhi - hlo + 1, nz = dhi - dlo + 1;
    if (nx > 0 && ny > 0 && nz > 0) {
        const float iH = im_info[0], iW = im_info[1], iD = im_info[2];
        int vol = nx * ny * nz;
        float vmax = 0.0f;
        for (int idx = threadIdx.x; idx < vol; idx += 256) {
            int x = idx % nx; int r = idx / nx;
            int y = r % ny;   int zc = r / ny;
            int w = wlo + x, h = hlo + y, d = dlo + zc;
            float shx = w * 16.0f, shy = h * 16.0f, shz = d * 16.0f;
            float ax1 = san[0] + shx, ay1 = san[1] + shy;
            float ax2 = san[2] + shx, ay2 = san[3] + shy;
            float az1 = san[4] + shz, az2 = san[5] + shz;
            bool inside = (ax1 >= 0.0f) && (ay1 >= 0.0f) && (az1 >= 0.0f) &&
                          (ax2 < iW) && (ay2 < iH) && (az2 < iD);
            if (!inside) continue;
            float aarea = f_area(ax1, ay1, ax2, ay2, az1, az2);
            float ov = f_ov(ax1, ay1, ax2, ay2, az1, az2, aarea, sg);
            vmax = fmaxf(vmax, ov);
        }
#pragma unroll
        for (int off = 16; off; off >>= 1)
            vmax = fmaxf(vmax, __shfl_xor_sync(0xFFFFFFFFu, vmax, off));
        if ((threadIdx.x & 31) == 0 && vmax > 0.0f) atomicMax(&smax, __float_as_int(vmax));
    }
    __syncthreads();
    if (threadIdx.x == 0 && smax > 0) atomicMax(&g_gtmax[b * NK + k], smax);
}

// ================= passB: labels, argmax, histogram (dense, exact) ===============
__global__ void __launch_bounds__(256, 3) k_passB(const float* __restrict__ gt,
                                                  const float* __restrict__ im_info,
                                                  const float* __restrict__ anchors,
                                                  const float* __restrict__ rfg,
                                                  const float* __restrict__ rbg) {
    int b    = blockIdx.x / BPB;
    int base = (blockIdx.x % BPB) * 2048;
    __shared__ float sgt[NK * 7];
    __shared__ float sgm[NK];
    __shared__ float sanch[NA * 6];
    build_sgt(sgt, gt, b);
    if (threadIdx.x < NK) {
        float gm = __int_as_float(g_gtmax[b * NK + threadIdx.x]);
        sgm[threadIdx.x] = (gm == 0.0f) ? 1e-5f : gm;
    }
    if (threadIdx.x < NA * 6) sanch[threadIdx.x] = anchors[threadIdx.x];
    __syncthreads();
    const float iH = im_info[0], iW = im_info[1], iD = im_info[2];

#pragma unroll 1
    for (int t = 0; t < 8; t++) {
        int i = base + t * 256 + threadIdx.x;
        int e = b * TOTAL + i;
        int a = i % NA; int q = i / NA;
        int d = q % ND; q /= ND;
        int w = q % NW; int h = q / NW;
        float shx = w * 16.0f, shy = h * 16.0f, shz = d * 16.0f;
        const float* an = sanch + a * 6;
        float ax1 = an[0] + shx, ay1 = an[1] + shy;
        float ax2 = an[2] + shx, ay2 = an[3] + shy;
        float az1 = an[4] + shz, az2 = an[5] + shz;
        bool inside = (ax1 >= 0.0f) && (ay1 >= 0.0f) && (az1 >= 0.0f) &&
                      (ax2 < iW) && (ay2 < iH) && (az2 < iD);
        signed char lab = -1;
        unsigned char am = 0;
        if (inside) {
            float aarea = f_area(ax1, ay1, ax2, ay2, az1, az2);
            float best = -1.0f;
            int bi = 0;
            bool tie = false;
#pragma unroll
            for (int k = 0; k < NK; k++) {
                float ov = f_ov(ax1, ay1, ax2, ay2, az1, az2, aarea, sgt + k * 7);
                if (ov > best) { best = ov; bi = k; }
                if (ov == sgm[k]) tie = true;
            }
            lab = (tie || best >= 0.7f) ? 1 : ((best < 0.3f) ? 0 : -1);
            am = (unsigned char)bi;
        }
        g_label[e] = lab;
        g_amax[e]  = am;

        if (lab == 1) {
            unsigned bin = __float_as_uint(rfg[e]) >> 16;
            atomicAdd(&g_hist[(b * 2) * NBINS + bin], 1u);
        } else if (lab == 0) {
            unsigned bin = __float_as_uint(rbg[e]) >> 16;
            atomicAdd(&g_hist[(b * 2 + 1) * NBINS + bin], 1u);
        }
    }
}

// ================= upd0: 256-block chunk sums + warp-parallel resolve ============
__global__ void __launch_bounds__(256) k_upd0() {
    int g = blockIdx.x >> 6;          // group 0..3
    int c = blockIdx.x & 63;          // chunk of 1024 bins
    const int tid = threadIdx.x;
    const int lane = tid & 31, wid = tid >> 5;

    uint4 v4 = ((const uint4*)(g_hist + g * NBINS + c * 1024))[tid];
    unsigned s = v4.x + v4.y + v4.z + v4.w;
#pragma unroll
    for (int off = 16; off; off >>= 1) s += __shfl_xor_sync(0xFFFFFFFFu, s, off);
    __shared__ unsigned wsum[8];
    __shared__ int slast;
    if (lane == 0) wsum[wid] = s;
    __syncthreads();
    if (tid == 0) {
        unsigned tot = 0;
#pragma unroll
        for (int i = 0; i < 8; i++) tot += wsum[i];
        g_csum[blockIdx.x] = tot;     // index = g*64 + c
        __threadfence();
        int o = atomicAdd(&g_done_u, 1);
        slast = (o == 255) ? 1 : 0;
    }
    __syncthreads();
    if (!slast) return;

    __shared__ unsigned scs[256];
    __shared__ unsigned stot[4];
    __shared__ unsigned sbins[4][1024];
    scs[tid] = g_csum[tid];
    __syncthreads();
    if (tid < 4) {
        unsigned t = 0;
        for (int j = 0; j < 64; j++) t += scs[tid * 64 + j];
        stot[tid] = t;
    }
    __syncthreads();
    if (tid == 0) {
        int fg1 = (int)stot[2]; if (fg1 > NUMFG) fg1 = NUMFG;
        int cap = RPNB - fg1;
        int bg1 = (int)stot[3]; if (bg1 > cap) bg1 = cap;
        int ne = fg1 + bg1;
        g_wval = 1.0f / (float)(ne > 0 ? ne : 1);
    }
    if (wid < 4) {
        int w = wid;
        unsigned total = stot[w];
        int m0;
        if ((w & 1) == 0) m0 = NUMFG;
        else { int fgc = (int)stot[w - 1]; int kept = (fgc < NUMFG) ? fgc : NUMFG; m0 = RPNB - kept; }

        if ((unsigned)m0 >= total) {
            if (lane == 0) { g_keep[w] = 1; g_thresh[w] = 0ULL; }
        } else {
            int cstar = 0; unsigned acc = 0;
            if (lane == 0) {
                for (int cc = 63; cc >= 0; cc--) {
                    unsigned cv = scs[w * 64 + cc];
                    if (acc + cv >= (unsigned)m0) { cstar = cc; break; }
                    acc += cv;
                }
            }
            cstar = __shfl_sync(0xFFFFFFFFu, cstar, 0);
            acc   = __shfl_sync(0xFFFFFFFFu, acc, 0);
            int m_rem = m0 - (int)acc;     // >= 1
            const unsigned* hb = g_hist + w * NBINS + cstar * 1024;
            for (int j = lane; j < 1024; j += 32) sbins[w][j] = hb[j];
            __syncwarp();
            unsigned accw = 0;
            for (int basei = 1023; basei >= 31; basei -= 32) {
                unsigned v = sbins[w][basei - lane];
                unsigned inc = v;
#pragma unroll
                for (int off = 1; off < 32; off <<= 1) {
                    unsigned u = __shfl_up_sync(0xFFFFFFFFu, inc, off);
                    if (lane >= off) inc += u;
                }
                unsigned tot32 = __shfl_sync(0xFFFFFFFFu, inc, 31);
                if (accw + tot32 >= (unsigned)m_rem) {
                    unsigned incl = accw + inc;
                    unsigned excl = incl - v;
                    if (excl < (unsigned)m_rem && (unsigned)m_rem <= incl) {
                        g_bin[w] = (unsigned)(cstar * 1024 + basei - lane);
                        g_m[w]   = m_rem - (int)excl;
                    }
                    break;
                }
                accw += tot32;
            }
        }
    }
}

// ================= collect: gather keys in the threshold bin =====================
__global__ void __launch_bounds__(256) k_collect(const float* __restrict__ rfg,
                                                 const float* __restrict__ rbg) {
    int e = blockIdx.x * 256 + threadIdx.x;
    int lab = g_label[e];
    if (lab < 0) return;
    int b = (e >= TOTAL) ? 1 : 0;
    unsigned i = (unsigned)(e - b * TOTAL);
    int grp = b * 2 + (lab == 0 ? 1 : 0);
    if (g_keep[grp]) return;
    float rv = (lab == 1) ? rfg[e] : rbg[e];
    unsigned rb = __float_as_uint(rv);
    if ((rb >> 16) != g_bin[grp]) return;
    unsigned long long key = ((unsigned long long)rb << 32) | (unsigned)(~i);
    int pos = atomicAdd(&g_ncand[grp], 1);
    if (pos < CAP) g_cand[grp * CAP + pos] = key;
}

// ================= finish: exact m-th largest within the bin =====================
__global__ void __launch_bounds__(256) k_finish() {
    int grp = blockIdx.x;
    if (g_keep[grp]) return;
    __shared__ unsigned long long sk[CAP];
    int n = g_ncand[grp];
    if (n > CAP) n = CAP;
    int m = g_m[grp];
    for (int i = threadIdx.x; i < n; i += 256) sk[i] = g_cand[grp * CAP + i];
    __syncthreads();
    for (int i = threadIdx.x; i < n; i += 256) {
        unsigned long long k = sk[i];
        int cg = 0;
        for (int j = 0; j < n; j++) cg += (sk[j] > k) ? 1 : 0;
        if (cg == m - 1) g_thresh[grp] = k;
    }
}

// ================= passD: outputs + state reset for next replay ==================
__global__ void __launch_bounds__(256) k_passD(const float* __restrict__ gt,
                                               const float* __restrict__ im_info,
                                               const float* __restrict__ anchors,
                                               const float* __restrict__ rfg,
                                               const float* __restrict__ rbg,
                                               float* __restrict__ out) {
    int tid = blockIdx.x * 256 + threadIdx.x;
    int idx = tid * 4;
    int d0 = idx % ND; int q = idx / ND;
    int w = q % NW; q /= NW;
    int h = q % NH; q /= NH;
    int a = q % NA; int b = q / NA;
    int pix0 = (h * NW + w) * ND + d0;

    __shared__ float sanch[NA * 6];
    __shared__ float sder[NA * 9];
    __shared__ float sgtd[NB * NK * 6];
    __shared__ unsigned long long sth[4];
    if (threadIdx.x < NA * 6) sanch[threadIdx.x] = anchors[threadIdx.x];
    if (threadIdx.x < 4) sth[threadIdx.x] = g_thresh[threadIdx.x];
    if (threadIdx.x >= 128 && threadIdx.x < 128 + NA) {
        int aa = threadIdx.x - 128;
        const float* an = anchors + aa * 6;
        float ew = an[2] - an[0] + 1.0f;
        float eh = an[3] - an[1] + 1.0f;
        float ed = an[5] - an[4] + 1.0f;
        float* o = sder + aa * 9;
        o[0] = an[0] + 0.5f * (ew - 1.0f);
        o[1] = an[1] + 0.5f * (eh - 1.0f);
        o[2] = an[4] + 0.5f * (ed - 1.0f);
        o[3] = 1.0f / ew; o[4] = 1.0f / eh; o[5] = 1.0f / ed;
        o[6] = logf(ew); o[7] = logf(eh); o[8] = logf(ed);
    }
    if (threadIdx.x >= 160 && threadIdx.x < 160 + NB * NK) {
        int j = threadIdx.x - 160;
        const float* g = gt + j * 7;
        float gw = g[2] - g[0] + 1.0f, gh = g[3] - g[1] + 1.0f, gd = g[5] - g[4] + 1.0f;
        float* o = sgtd + j * 6;
        o[0] = g[0] + 0.5f * (gw - 1.0f);
        o[1] = g[1] + 0.5f * (gh - 1.0f);
        o[2] = g[4] + 0.5f * (gd - 1.0f);
        o[3] = logf(gw); o[4] = logf(gh); o[5] = logf(gd);
    }
    __syncthreads();

    const float iH = im_info[0], iW = im_info[1], iD = im_info[2];
    const float* an = sanch + a * 6;
    const float* ad = sder + a * 9;
    float shx = w * 16.0f, shy = h * 16.0f;
    float ax1 = an[0] + shx, ay1 = an[1] + shy;
    float ax2 = an[2] + shx, ay2 = an[3] + shy;
    bool inxy = (ax1 >= 0.0f) && (ay1 >= 0.0f) && (ax2 < iW) && (ay2 < iH);
    float wv = g_wval;

    float lb[4], ivv[4], ovv[4];
    float T[6][4];
#pragma unroll
    for (int j = 0; j < 4; j++) {
        float shz = (float)(d0 + j) * 16.0f;
        float az1 = an[4] + shz, az2 = an[5] + shz;
        bool inside = inxy && (az1 >= 0.0f) && (az2 < iD);
        int ia = (pix0 + j) * NA + a;
        int e  = b * TOTAL + ia;
        int lab = (int)g_label[e];
        if (lab >= 0) {
            int grp = b * 2 + (lab == 0 ? 1 : 0);
            float rv = (lab == 1) ? rfg[e] : rbg[e];
            unsigned long long key = ((unsigned long long)__float_as_uint(rv) << 32) | (unsigned)(~(unsigned)ia);
            if (key < sth[grp]) lab = -1;
        }
        float t0 = 0.0f, t1 = 0.0f, t2 = 0.0f, t3 = 0.0f, t4 = 0.0f, t5 = 0.0f;
        if (inside) {
            int am = (int)g_amax[e];
            const float* gd = sgtd + (b * NK + am) * 6;
            t0 = (gd[0] - ad[0] - shx) * ad[3];
            t1 = (gd[1] - ad[1] - shy) * ad[4];
            t2 = (gd[2] - ad[2] - shz) * ad[5];
            t3 = gd[3] - ad[6];
            t4 = gd[4] - ad[7];
            t5 = gd[5] - ad[8];
        }
        T[0][j] = t0; T[1][j] = t1; T[2][j] = t2;
        T[3][j] = t3; T[4][j] = t4; T[5][j] = t5;
        lb[j]  = (float)lab;
        ivv[j] = (lab == 1) ? 1.0f : 0.0f;
        ovv[j] = (lab >= 0) ? wv : 0.0f;
    }

    *(float4*)(out + idx) = make_float4(lb[0], lb[1], lb[2], lb[3]);
    long long base = (long long)(b * 54 + a * 6) * HWD + pix0;
    float* bt = out + OFF_BT + base;
#pragma unroll
    for (int c = 0; c < 6; c++)
        *(float4*)(bt + c * HWD) = make_float4(T[c][0], T[c][1], T[c][2], T[c][3]);
    float* iwp = out + OFF_IW + base;
    float* owp = out + OFF_OW + base;
    float4 iv = make_float4(ivv[0], ivv[1], ivv[2], ivv[3]);
    float4 ov = make_float4(ovv[0], ovv[1], ovv[2], ovv[3]);
#pragma unroll
    for (int c = 0; c < 6; c++) {
        *(float4*)(iwp + c * HWD) = iv;
        *(float4*)(owp + c * HWD) = ov;
    }

    // ---- state reset for the next graph replay (block 0; values unused below) ----
    if (blockIdx.x == 0) {
        int t = threadIdx.x;
        if (t < NB * NK) g_gtmax[t] = 0;
        if (t >= 72 && t < 76)  g_ncand[t - 72] = 0;
        if (t >= 80 && t < 84)  g_keep[t - 80] = 0;
        if (t == 90) g_done_u = 0;
    }
}

// ---------------- launch ----------------
extern "C" void kernel_launch(void* const* d_in, const int* in_sizes, int n_in,
                              void* d_out, int out_size) {
    const float* gt      = (const float*)d_in[1];
    const float* im_info = (const float*)d_in[2];
    const float* anchors = (const float*)d_in[4];
    const float* rfg     = (const float*)d_in[5];
    const float* rbg     = (const float*)d_in[6];
    float* out           = (float*)d_out;

    k_passA<<<512, 256>>>(gt, im_info, anchors);
    k_passB<<<NB * BPB, 256>>>(gt, im_info, anchors, rfg, rbg);
    k_upd0<<<256, 256>>>();
    k_collect<<<(NB * TOTAL) / 256, 256>>>(rfg, rbg);
    k_finish<<<4, 256>>>();
    k_passD<<<OUTTOT / 4 / 256, 256>>>(gt, im_info, anchors, rfg, rbg, out);
}

// round 14
// speedup vs baseline: 1.4426x; 1.0066x over previous
#include <cuda_runtime.h>
#include <cuda_bf16.h>
#include <stdint.h>

#define NB 2
#define NH 48
#define NW 48
#define ND 24
#define NA 9
#define NK 20
#define TOTAL  497664            // NH*NW*ND*NA
#define HWD    55296             // NH*NW*ND
#define OUTTOT 995328            // NB*NA*HWD
#define NUMFG 128
#define RPNB  256
#define NBINS 65536
#define CAP   4096
#define BPB   243                // blocks per batch in passB (2048 anchors each)

#define OFF_BT  995328
#define OFF_IW  (OFF_BT + 5971968)
#define OFF_OW  (OFF_IW + 5971968)

// ------------- device scratch (zero-init at load; reset by passD block 0) -------
__device__ int                g_gtmax[NB * NK];     // float bits of max ov (>=0); 0-init ok
__device__ signed char        g_label[NB * TOTAL];
__device__ unsigned char      g_amax[NB * TOTAL];
__device__ unsigned int       g_hist[4 * NBINS];
__device__ unsigned int       g_csum[256];
__device__ unsigned int       g_bin[4];
__device__ int                g_m[4];
__device__ int                g_keep[4];            // 1 => keep all (0-init = active)
__device__ int                g_ncand[4];
__device__ unsigned long long g_cand[4 * CAP];
__device__ unsigned long long g_thresh[4];
__device__ int                g_done_u;
__device__ float              g_wval;

// IoU with strict _rn intrinsics: bitwise identical in passA and passB.
__device__ __forceinline__ float f_ov(float ax1, float ay1, float ax2, float ay2,
                                      float az1, float az2, float aarea,
                                      const float* __restrict__ g) {
    float iw = __fadd_rn(__fsub_rn(fminf(ax2, g[2]), fmaxf(ax1, g[0])), 1.0f);
    if (iw <= 0.0f) return 0.0f;
    float ih = __fadd_rn(__fsub_rn(fminf(ay2, g[3]), fmaxf(ay1, g[1])), 1.0f);
    if (ih <= 0.0f) return 0.0f;
    float idp = __fadd_rn(__fsub_rn(fminf(az2, g[5]), fmaxf(az1, g[4])), 1.0f);
    if (idp <= 0.0f) return 0.0f;
    float inter = __fmul_rn(__fmul_rn(iw, ih), idp);
    float den   = __fsub_rn(__fadd_rn(aarea, g[6]), inter);
    return __fdiv_rn(inter, den);
}

__device__ __forceinline__ float f_area(float x1, float y1, float x2, float y2,
                                        float z1, float z2) {
    float aw = __fadd_rn(__fsub_rn(x2, x1), 1.0f);
    float ah = __fadd_rn(__fsub_rn(y2, y1), 1.0f);
    float ad = __fadd_rn(__fsub_rn(z2, z1), 1.0f);
    return __fmul_rn(__fmul_rn(aw, ah), ad);
}

__device__ __forceinline__ void build_sgt(float* sgt, const float* __restrict__ gt, int b) {
    int tid = threadIdx.x;
    if (tid < NK) {
        const float* g = gt + (b * NK + tid) * 7;
        float x1 = g[0], y1 = g[1], x2 = g[2], y2 = g[3], z1 = g[4], z2 = g[5];
        float gw = __fadd_rn(__fsub_rn(x2, x1), 1.0f);
        float gh = __fadd_rn(__fsub_rn(y2, y1), 1.0f);
        float gd = __fadd_rn(__fsub_rn(z2, z1), 1.0f);
        if (gw == 1.0f && gh == 1.0f && gd == 1.0f) { x2 = -1e9f; }   // zero-size => ov 0
        float* o = sgt + tid * 7;
        o[0] = x1; o[1] = y1; o[2] = x2; o[3] = y2; o[4] = z1; o[5] = z2;
        o[6] = __fmul_rn(__fmul_rn(gw, gh), gd);
    }
}

// ===== passA: hist zero (512 blocks x 128 uint4) + windowed per-(b,gt,a) max =====
__global__ void __launch_bounds__(256) k_passA(const float* __restrict__ gt,
                                               const float* __restrict__ im_info,
                                               const float* __restrict__ anchors) {
    // zero histogram: 512 blocks x 128 uint4 = 65536 uint4
    if (threadIdx.x < 128)
        ((uint4*)g_hist)[blockIdx.x * 128 + threadIdx.x] = make_uint4(0u, 0u, 0u, 0u);
    if (blockIdx.x >= NB * NK * NA) return;

    int b = blockIdx.x / (NK * NA);
    int k = (blockIdx.x / NA) % NK;
    int a = blockIdx.x % NA;

    __shared__ float sg[7];
    __shared__ float san[6];
    __shared__ int   smax;
    if (threadIdx.x == 0) {
        const float* g = gt + (b * NK + k) * 7;
        float x1 = g[0], y1 = g[1], x2 = g[2], y2 = g[3], z1 = g[4], z2 = g[5];
        float gw = __fadd_rn(__fsub_rn(x2, x1), 1.0f);
        float gh = __fadd_rn(__fsub_rn(y2, y1), 1.0f);
        float gd = __fadd_rn(__fsub_rn(z2, z1), 1.0f);
        if (gw == 1.0f && gh == 1.0f && gd == 1.0f) { x2 = -1e9f; }
        sg[0] = x1; sg[1] = y1; sg[2] = x2; sg[3] = y2; sg[4] = z1; sg[5] = z2;
        sg[6] = __fmul_rn(__fmul_rn(gw, gh), gd);
        smax = 0;
    }
    if (threadIdx.x >= 32 && threadIdx.x < 38) san[threadIdx.x - 32] = anchors[a * 6 + threadIdx.x - 32];
    __syncthreads();

    // shift window where ov>0 is possible (±1 cell slack; validated in R12)
    int wlo = max(0,      (int)floorf((sg[0] - 1.0f - san[2]) * 0.0625f) - 1);
    int whi = min(NW - 1, (int)floorf((sg[2] + 1.0f - san[0]) * 0.0625f) + 1);
    int hlo = max(0,      (int)floorf((sg[1] - 1.0f - san[3]) * 0.0625f) - 1);
    int hhi = min(NH - 1, (int)floorf((sg[3] + 1.0f - san[1]) * 0.0625f) + 1);
    int dlo = max(0,      (int)floorf((sg[4] - 1.0f - san[5]) * 0.0625f) - 1);
    int dhi = min(ND - 1, (int)floorf((sg[5] + 1.0f - san[4]) * 0.0625f) + 1);
    int nx = whi - wlo + 1, ny = hhi - hlo + 1, nz = dhi - dlo + 1;
    if (nx > 0 && ny > 0 && nz > 0) {
        const float iH = im_info[0], iW = im_info[1], iD = im_info[2];
        int vol = nx * ny * nz;
        float vmax = 0.0f;
        for (int idx = threadIdx.x; idx < vol; idx += 256) {
            int x = idx % nx; int r = idx / nx;
            int y = r % ny;   int zc = r / ny;
            int w = wlo + x, h = hlo + y, d = dlo + zc;
            float shx = w * 16.0f, shy = h * 16.0f, shz = d * 16.0f;
            float ax1 = san[0] + shx, ay1 = san[1] + shy;
            float ax2 = san[2] + shx, ay2 = san[3] + shy;
            float az1 = san[4] + shz, az2 = san[5] + shz;
            bool inside = (ax1 >= 0.0f) && (ay1 >= 0.0f) && (az1 >= 0.0f) &&
                          (ax2 < iW) && (ay2 < iH) && (az2 < iD);
            if (!inside) continue;
            float aarea = f_area(ax1, ay1, ax2, ay2, az1, az2);
            float ov = f_ov(ax1, ay1, ax2, ay2, az1, az2, aarea, sg);
            vmax = fmaxf(vmax, ov);
        }
#pragma unroll
        for (int off = 16; off; off >>= 1)
            vmax = fmaxf(vmax, __shfl_xor_sync(0xFFFFFFFFu, vmax, off));
        if ((threadIdx.x & 31) == 0 && vmax > 0.0f) atomicMax(&smax, __float_as_int(vmax));
    }
    __syncthreads();
    if (threadIdx.x == 0 && smax > 0) atomicMax(&g_gtmax[b * NK + k], smax);
}

// ================= passB: labels, argmax, histogram (dense, exact) ===============
__global__ void __launch_bounds__(256, 3) k_passB(const float* __restrict__ gt,
                                                  const float* __restrict__ im_info,
                                                  const float* __restrict__ anchors,
                                                  const float* __restrict__ rfg,
                                                  const float* __restrict__ rbg) {
    int b    = blockIdx.x / BPB;
    int base = (blockIdx.x % BPB) * 2048;
    __shared__ float sgt[NK * 7];
    __shared__ float sgm[NK];
    __shared__ float sanch[NA * 6];
    build_sgt(sgt, gt, b);
    if (threadIdx.x < NK) {
        float gm = __int_as_float(g_gtmax[b * NK + threadIdx.x]);
        sgm[threadIdx.x] = (gm == 0.0f) ? 1e-5f : gm;
    }
    if (threadIdx.x < NA * 6) sanch[threadIdx.x] = anchors[threadIdx.x];
    __syncthreads();
    const float iH = im_info[0], iW = im_info[1], iD = im_info[2];

#pragma unroll 1
    for (int t = 0; t < 8; t++) {
        int i = base + t * 256 + threadIdx.x;
        int e = b * TOTAL + i;
        int a = i % NA; int q = i / NA;
        int d = q % ND; q /= ND;
        int w = q % NW; int h = q / NW;
        float shx = w * 16.0f, shy = h * 16.0f, shz = d * 16.0f;
        const float* an = sanch + a * 6;
        float ax1 = an[0] + shx, ay1 = an[1] + shy;
        float ax2 = an[2] + shx, ay2 = an[3] + shy;
        float az1 = an[4] + shz, az2 = an[5] + shz;
        bool inside = (ax1 >= 0.0f) && (ay1 >= 0.0f) && (az1 >= 0.0f) &&
                      (ax2 < iW) && (ay2 < iH) && (az2 < iD);
        signed char lab = -1;
        unsigned char am = 0;
        if (inside) {
            float aarea = f_area(ax1, ay1, ax2, ay2, az1, az2);
            float best = -1.0f;
            int bi = 0;
            bool tie = false;
#pragma unroll
            for (int k = 0; k < NK; k++) {
                float ov = f_ov(ax1, ay1, ax2, ay2, az1, az2, aarea, sgt + k * 7);
                if (ov > best) { best = ov; bi = k; }
                if (ov == sgm[k]) tie = true;
            }
            lab = (tie || best >= 0.7f) ? 1 : ((best < 0.3f) ? 0 : -1);
            am = (unsigned char)bi;
        }
        g_label[e] = lab;
        g_amax[e]  = am;

        if (lab == 1) {
            unsigned bin = __float_as_uint(rfg[e]) >> 16;
            atomicAdd(&g_hist[(b * 2) * NBINS + bin], 1u);
        } else if (lab == 0) {
            unsigned bin = __float_as_uint(rbg[e]) >> 16;
            atomicAdd(&g_hist[(b * 2 + 1) * NBINS + bin], 1u);
        }
    }
}

// ================= upd0: 256-block chunk sums + warp-parallel resolve ============
__global__ void __launch_bounds__(256) k_upd0() {
    int g = blockIdx.x >> 6;          // group 0..3
    int c = blockIdx.x & 63;          // chunk of 1024 bins
    const int tid = threadIdx.x;
    const int lane = tid & 31, wid = tid >> 5;

    uint4 v4 = ((const uint4*)(g_hist + g * NBINS + c * 1024))[tid];
    unsigned s = v4.x + v4.y + v4.z + v4.w;
#pragma unroll
    for (int off = 16; off; off >>= 1) s += __shfl_xor_sync(0xFFFFFFFFu, s, off);
    __shared__ unsigned wsum[8];
    __shared__ int slast;
    if (lane == 0) wsum[wid] = s;
    __syncthreads();
    if (tid == 0) {
        unsigned tot = 0;
#pragma unroll
        for (int i = 0; i < 8; i++) tot += wsum[i];
        g_csum[blockIdx.x] = tot;     // index = g*64 + c
        __threadfence();
        int o = atomicAdd(&g_done_u, 1);
        slast = (o == 255) ? 1 : 0;
    }
    __syncthreads();
    if (!slast) return;

    __shared__ unsigned scs[256];
    __shared__ unsigned stot[4];
    __shared__ unsigned sbins[4][1024];
    scs[tid] = g_csum[tid];
    __syncthreads();
    if (tid < 4) {
        unsigned t = 0;
        for (int j = 0; j < 64; j++) t += scs[tid * 64 + j];
        stot[tid] = t;
    }
    __syncthreads();
    if (tid == 0) {
        int fg1 = (int)stot[2]; if (fg1 > NUMFG) fg1 = NUMFG;
        int cap = RPNB - fg1;
        int bg1 = (int)stot[3]; if (bg1 > cap) bg1 = cap;
        int ne = fg1 + bg1;
        g_wval = 1.0f / (float)(ne > 0 ? ne : 1);
    }
    if (wid < 4) {
        int w = wid;
        unsigned total = stot[w];
        int m0;
        if ((w & 1) == 0) m0 = NUMFG;
        else { int fgc = (int)stot[w - 1]; int kept = (fgc < NUMFG) ? fgc : NUMFG; m0 = RPNB - kept; }

        if ((unsigned)m0 >= total) {
            if (lane == 0) { g_keep[w] = 1; g_thresh[w] = 0ULL; }
        } else {
            int cstar = 0; unsigned acc = 0;
            if (lane == 0) {
                for (int cc = 63; cc >= 0; cc--) {
                    unsigned cv = scs[w * 64 + cc];
                    if (acc + cv >= (unsigned)m0) { cstar = cc; break; }
                    acc += cv;
                }
            }
            cstar = __shfl_sync(0xFFFFFFFFu, cstar, 0);
            acc   = __shfl_sync(0xFFFFFFFFu, acc, 0);
            int m_rem = m0 - (int)acc;     // >= 1
            const unsigned* hb = g_hist + w * NBINS + cstar * 1024;
            for (int j = lane; j < 1024; j += 32) sbins[w][j] = hb[j];
            __syncwarp();
            unsigned accw = 0;
            for (int basei = 1023; basei >= 31; basei -= 32) {
                unsigned v = sbins[w][basei - lane];
                unsigned inc = v;
#pragma unroll
                for (int off = 1; off < 32; off <<= 1) {
                    unsigned u = __shfl_up_sync(0xFFFFFFFFu, inc, off);
                    if (lane >= off) inc += u;
                }
                unsigned tot32 = __shfl_sync(0xFFFFFFFFu, inc, 31);
                if (accw + tot32 >= (unsigned)m_rem) {
                    unsigned incl = accw + inc;
                    unsigned excl = incl - v;
                    if (excl < (unsigned)m_rem && (unsigned)m_rem <= incl) {
                        g_bin[w] = (unsigned)(cstar * 1024 + basei - lane);
                        g_m[w]   = m_rem - (int)excl;
                    }
                    break;
                }
                accw += tot32;
            }
        }
    }
}

// ================= collect: gather keys in the threshold bin =====================
__global__ void __launch_bounds__(256) k_collect(const float* __restrict__ rfg,
                                                 const float* __restrict__ rbg) {
    int e = blockIdx.x * 256 + threadIdx.x;
    int lab = g_label[e];
    if (lab < 0) return;
    int b = (e >= TOTAL) ? 1 : 0;
    unsigned i = (unsigned)(e - b * TOTAL);
    int grp = b * 2 + (lab == 0 ? 1 : 0);
    if (g_keep[grp]) return;
    float rv = (lab == 1) ? rfg[e] : rbg[e];
    unsigned rb = __float_as_uint(rv);
    if ((rb >> 16) != g_bin[grp]) return;
    unsigned long long key = ((unsigned long long)rb << 32) | (unsigned)(~i);
    int pos = atomicAdd(&g_ncand[grp], 1);
    if (pos < CAP) g_cand[grp * CAP + pos] = key;
}

// ================= finish: exact m-th largest within the bin =====================
__global__ void __launch_bounds__(256) k_finish() {
    int grp = blockIdx.x;
    if (g_keep[grp]) return;
    __shared__ unsigned long long sk[CAP];
    int n = g_ncand[grp];
    if (n > CAP) n = CAP;
    int m = g_m[grp];
    for (int i = threadIdx.x; i < n; i += 256) sk[i] = g_cand[grp * CAP + i];
    __syncthreads();
    for (int i = threadIdx.x; i < n; i += 256) {
        unsigned long long k = sk[i];
        int cg = 0;
        for (int j = 0; j < n; j++) cg += (sk[j] > k) ? 1 : 0;
        if (cg == m - 1) g_thresh[grp] = k;
    }
}

// ================= passD: outputs + state reset for next replay ==================
__global__ void __launch_bounds__(256) k_passD(const float* __restrict__ gt,
                                               const float* __restrict__ im_info,
                                               const float* __restrict__ anchors,
                                               const float* __restrict__ rfg,
                                               const float* __restrict__ rbg,
                                               float* __restrict__ out) {
    int tid = blockIdx.x * 256 + threadIdx.x;
    int idx = tid * 4;
    int d0 = idx % ND; int q = idx / ND;
    int w = q % NW; q /= NW;
    int h = q % NH; q /= NH;
    int a = q % NA; int b = q / NA;
    int pix0 = (h * NW + w) * ND + d0;

    __shared__ float sanch[NA * 6];
    __shared__ float sder[NA * 9];
    __shared__ float sgtd[NB * NK * 6];
    __shared__ unsigned long long sth[4];
    if (threadIdx.x < NA * 6) sanch[threadIdx.x] = anchors[threadIdx.x];
    if (threadIdx.x < 4) sth[threadIdx.x] = g_thresh[threadIdx.x];
    if (threadIdx.x >= 128 && threadIdx.x < 128 + NA) {
        int aa = threadIdx.x - 128;
        const float* an = anchors + aa * 6;
        float ew = an[2] - an[0] + 1.0f;
        float eh = an[3] - an[1] + 1.0f;
        float ed = an[5] - an[4] + 1.0f;
        float* o = sder + aa * 9;
        o[0] = an[0] + 0.5f * (ew - 1.0f);
        o[1] = an[1] + 0.5f * (eh - 1.0f);
        o[2] = an[4] + 0.5f * (ed - 1.0f);
        o[3] = 1.0f / ew; o[4] = 1.0f / eh; o[5] = 1.0f / ed;
        o[6] = logf(ew); o[7] = logf(eh); o[8] = logf(ed);
    }
    if (threadIdx.x >= 160 && threadIdx.x < 160 + NB * NK) {
        int j = threadIdx.x - 160;
        const float* g = gt + j * 7;
        float gw = g[2] - g[0] + 1.0f, gh = g[3] - g[1] + 1.0f, gd = g[5] - g[4] + 1.0f;
        float* o = sgtd + j * 6;
        o[0] = g[0] + 0.5f * (gw - 1.0f);
        o[1] = g[1] + 0.5f * (gh - 1.0f);
        o[2] = g[4] + 0.5f * (gd - 1.0f);
        o[3] = logf(gw); o[4] = logf(gh); o[5] = logf(gd);
    }
    __syncthreads();

    const float iH = im_info[0], iW = im_info[1], iD = im_info[2];
    const float* an = sanch + a * 6;
    const float* ad = sder + a * 9;
    float shx = w * 16.0f, shy = h * 16.0f;
    float ax1 = an[0] + shx, ay1 = an[1] + shy;
    float ax2 = an[2] + shx, ay2 = an[3] + shy;
    bool inxy = (ax1 >= 0.0f) && (ay1 >= 0.0f) && (ax2 < iW) && (ay2 < iH);
    float wv = g_wval;

    float lb[4], ivv[4], ovv[4];
    float T[6][4];
#pragma unroll
    for (int j = 0; j < 4; j++) {
        float shz = (float)(d0 + j) * 16.0f;
        float az1 = an[4] + shz, az2 = an[5] + shz;
        bool inside = inxy && (az1 >= 0.0f) && (az2 < iD);
        int ia = (pix0 + j) * NA + a;
        int e  = b * TOTAL + ia;
        int lab = (int)g_label[e];
        if (lab >= 0) {
            int grp = b * 2 + (lab == 0 ? 1 : 0);
            float rv = (lab == 1) ? rfg[e] : rbg[e];
            unsigned long long key = ((unsigned long long)__float_as_uint(rv) << 32) | (unsigned)(~(unsigned)ia);
            if (key < sth[grp]) lab = -1;
        }
        float t0 = 0.0f, t1 = 0.0f, t2 = 0.0f, t3 = 0.0f, t4 = 0.0f, t5 = 0.0f;
        if (inside) {
            int am = (int)g_amax[e];
            const float* gd = sgtd + (b * NK + am) * 6;
            t0 = (gd[0] - ad[0] - shx) * ad[3];
            t1 = (gd[1] - ad[1] - shy) * ad[4];
            t2 = (gd[2] - ad[2] - shz) * ad[5];
            t3 = gd[3] - ad[6];
            t4 = gd[4] - ad[7];
            t5 = gd[5] - ad[8];
        }
        T[0][j] = t0; T[1][j] = t1; T[2][j] = t2;
        T[3][j] = t3; T[4][j] = t4; T[5][j] = t5;
        lb[j]  = (float)lab;
        ivv[j] = (lab == 1) ? 1.0f : 0.0f;
        ovv[j] = (lab >= 0) ? wv : 0.0f;
    }

    *(float4*)(out + idx) = make_float4(lb[0], lb[1], lb[2], lb[3]);
    long long base = (long long)(b * 54 + a * 6) * HWD + pix0;
    float* bt = out + OFF_BT + base;
#pragma unroll
    for (int c = 0; c < 6; c++)
        *(float4*)(bt + c * HWD) = make_float4(T[c][0], T[c][1], T[c][2], T[c][3]);
    float* iwp = out + OFF_IW + base;
    float* owp = out + OFF_OW + base;
    float4 iv = make_float4(ivv[0], ivv[1], ivv[2], ivv[3]);
    float4 ov = make_float4(ovv[0], ovv[1], ovv[2], ovv[3]);
#pragma unroll
    for (int c = 0; c < 6; c++) {
        *(float4*)(iwp + c * HWD) = iv;
        *(float4*)(owp + c * HWD) = ov;
    }

    // ---- state reset for the next graph replay (block 0; values unused below) ----
    if (blockIdx.x == 0) {
        int t = threadIdx.x;
        if (t < NB * NK) g_gtmax[t] = 0;
        if (t >= 72 && t < 76)  g_ncand[t - 72] = 0;
        if (t >= 80 && t < 84)  g_keep[t - 80] = 0;
        if (t == 90) g_done_u = 0;
    }
}

// ---------------- launch ----------------
extern "C" void kernel_launch(void* const* d_in, const int* in_sizes, int n_in,
                              void* d_out, int out_size) {
    const float* gt      = (const float*)d_in[1];
    const float* im_info = (const float*)d_in[2];
    const float* anchors = (const float*)d_in[4];
    const float* rfg     = (const float*)d_in[5];
    const float* rbg     = (const float*)d_in[6];
    float* out           = (float*)d_out;

    k_passA<<<512, 256>>>(gt, im_info, anchors);
    k_passB<<<NB * BPB, 256>>>(gt, im_info, anchors, rfg, rbg);
    k_upd0<<<256, 256>>>();
    k_collect<<<(NB * TOTAL) / 256, 256>>>(rfg, rbg);
    k_finish<<<4, 256>>>();
    k_passD<<<OUTTOT / 4 / 256, 256>>>(gt, im_info, anchors, rfg, rbg, out);
}